// round 7
// baseline (speedup 1.0000x reference)
#include <cuda_runtime.h>
#include <math.h>

#define Bc 2
#define Sc 2048
#define Dc 1024
#define Hc 16
#define DKc 64
#define BSc (Bc*Sc)   // 4096

// Scratch (no allocations allowed)
__device__ float g_qkv[(size_t)BSc * 3 * Dc];      // [B,S,3,H,DK]
__device__ float g_q[(size_t)Bc*Hc*Sc*DKc];        // [B,H,S,DK]
__device__ float g_k[(size_t)Bc*Hc*Sc*DKc];
__device__ float g_v[(size_t)Bc*Hc*Sc*DKc];
__device__ float g_attn[(size_t)BSc * Dc];         // [B,S,D]
__device__ float g_ctab[Sc * 32];                  // RoPE cos table
__device__ float g_stab[Sc * 32];                  // RoPE sin table

// ---------------------------------------------------------------------------
// Classic 128x128x8 SGEMM (unchanged)
// ---------------------------------------------------------------------------
__global__ void sgemm_kernel(const float* __restrict__ A,
                             const float* __restrict__ Bm,
                             float* __restrict__ C,
                             int M, int N, int K) {
    __shared__ float As[8 * 132];
    __shared__ float Bs[8 * 128];

    const int tid = threadIdx.x;
    const int tx = tid & 15;
    const int ty = tid >> 4;
    const int m0 = blockIdx.y << 7;
    const int n0 = blockIdx.x << 7;

    float acc[8][8];
#pragma unroll
    for (int i = 0; i < 8; i++)
#pragma unroll
        for (int j = 0; j < 8; j++) acc[i][j] = 0.f;

    for (int k0 = 0; k0 < K; k0 += 8) {
#pragma unroll
        for (int i = 0; i < 4; i++) {
            int e = tid + (i << 8);
            int m = e >> 3, kk = e & 7;
            As[kk * 132 + m] = A[(size_t)(m0 + m) * K + k0 + kk];
        }
#pragma unroll
        for (int i = 0; i < 4; i++) {
            int e = tid + (i << 8);
            int kk = e >> 7, n = e & 127;
            Bs[kk * 128 + n] = Bm[(size_t)(k0 + kk) * N + n0 + n];
        }
        __syncthreads();

#pragma unroll
        for (int kk = 0; kk < 8; kk++) {
            float a[8], bb[8];
#pragma unroll
            for (int i = 0; i < 8; i++) a[i] = As[kk * 132 + ty * 8 + i];
#pragma unroll
            for (int j = 0; j < 8; j++) bb[j] = Bs[kk * 128 + tx * 8 + j];
#pragma unroll
            for (int i = 0; i < 8; i++)
#pragma unroll
                for (int j = 0; j < 8; j++) acc[i][j] += a[i] * bb[j];
        }
        __syncthreads();
    }

#pragma unroll
    for (int i = 0; i < 8; i++)
#pragma unroll
        for (int j = 0; j < 8; j++)
            C[(size_t)(m0 + ty * 8 + i) * N + n0 + tx * 8 + j] = acc[i][j];
}

// ---------------------------------------------------------------------------
// RoPE table precompute: [S][32] cos/sin, same math as before (exact match)
// ---------------------------------------------------------------------------
__global__ void rope_table_kernel() {
    int idx = blockIdx.x * blockDim.x + threadIdx.x;   // s*32 + d2
    int d2 = idx & 31;
    int s = idx >> 5;
    float invf = 1.0f / powf(10000.0f, (float)d2 * (1.0f / 32.0f));
    float ang = (float)s * invf;
    float sn, c;
    sincosf(ang, &sn, &c);
    g_ctab[idx] = c;
    g_stab[idx] = sn;
}

// ---------------------------------------------------------------------------
// RoPE + split heads, table-driven (pure memory now)
// ---------------------------------------------------------------------------
__global__ void rope_split_kernel(const float* __restrict__ qkv,
                                  float* __restrict__ Q,
                                  float* __restrict__ Kp,
                                  float* __restrict__ V) {
    int idx = blockIdx.x * blockDim.x + threadIdx.x;  // [b][s][h][d]
    int d = idx & 63;
    int h = (idx >> 6) & (Hc - 1);
    int s = (idx >> 10) & (Sc - 1);
    int b = idx >> 21;

    const float* base = qkv + (size_t)(b * Sc + s) * 3 * Dc + h * DKc;
    float qv = base[d];
    float kv = base[Dc + d];
    float vv = base[2 * Dc + d];

    int d2 = d & 31;
    float c = g_ctab[s * 32 + d2];
    float sn = g_stab[s * 32 + d2];

    int dp = d ^ 32;            // rotate_half partner
    float qp = base[dp];
    float kp = base[Dc + dp];
    float sgn = (d < 32) ? -1.0f : 1.0f;

    float qo = qv * c + sgn * qp * sn;
    float ko = kv * c + sgn * kp * sn;

    size_t o = ((size_t)(b * Hc + h) * Sc + s) * DKc + d;
    Q[o] = qo;
    Kp[o] = ko;
    V[o] = vv;
}

// ---------------------------------------------------------------------------
// Flash attention v5: tf32 mma.sync, Br=128, Bc=64, 8 warps.
// Fragment-packed SMEM: every mma operand load is one conflict-free LDS.64.
//   Qp/Pp: uint2 pair {A[r][k], A[r+8][k]} at [rowgrp*68 + k]   (a-fragments)
//   Kp/Vp: uint2 pair {B[k][n], B[k+4][n]}  at [mma*32 + lane]  (b-fragments)
// ---------------------------------------------------------------------------
#define UQ 68               // a-fragment row-group stride in uint2 (bank-safe)
#define QTILES (Sc / 128)   // 16

__device__ __forceinline__ unsigned f2tf(float x) {
    unsigned r;
    asm("cvt.rna.tf32.f32 %0, %1;" : "=r"(r) : "f"(x));
    return r;
}

__device__ __forceinline__ void mma8(float4& d, uint2 a01, uint2 a23, uint2 b) {
    asm volatile(
        "mma.sync.aligned.m16n8k8.row.col.f32.tf32.tf32.f32 "
        "{%0,%1,%2,%3}, {%4,%5,%6,%7}, {%8,%9}, {%0,%1,%2,%3};\n"
        : "+f"(d.x), "+f"(d.y), "+f"(d.z), "+f"(d.w)
        : "r"(a01.x), "r"(a01.y), "r"(a23.x), "r"(a23.y), "r"(b.x), "r"(b.y));
}

__global__ __launch_bounds__(256, 2)
void flash_attn_kernel(const float* __restrict__ Q,
                       const float* __restrict__ K,
                       const float* __restrict__ V,
                       float* __restrict__ Out) {
    extern __shared__ uint2 sm2[];
    uint2* Qp = sm2;                  // [64 rowgrps][UQ]
    uint2* Pp = Qp + 64 * UQ;         // [64 rowgrps][UQ]
    uint2* Kp = Pp + 64 * UQ;         // [64 mma][32 lane]
    uint2* Vp = Kp + 2048;            // [64 mma][32 lane]

    const int tid = threadIdx.x;      // 256 threads
    const int lane = tid & 31;
    const int w = tid >> 5;           // warp 0..7
    const int g = lane >> 2;
    const int tig = lane & 3;

    // Heavy-first scheduling: qt descending with blockIdx.x
    const int id = blockIdx.x;
    const int bh = id & 31;                  // b*H + h
    const int qt = (QTILES - 1) - (id >> 5);
    const int q0 = qt * 128;

    const float* Qb = Q + (size_t)bh * Sc * DKc;
    const float* Kb = K + (size_t)bh * Sc * DKc;
    const float* Vb = V + (size_t)bh * Sc * DKc;

    // ---- Q pack prologue: pairs {Q[r][d], Q[r+8][d]}, pre-scaled ----
#pragma unroll
    for (int it = 0; it < 4; it++) {
        int e = tid + it * 256;        // 1024 assignments
        int rg = e >> 4;               // rowgroup 0..63  (= wq*8 + gq)
        int dq = e & 15;               // d-quad
        int r0 = q0 + (rg >> 3) * 16 + (rg & 7);
        float4 f0 = *(const float4*)&Qb[(size_t)r0 * DKc + dq * 4];
        float4 f1 = *(const float4*)&Qb[(size_t)(r0 + 8) * DKc + dq * 4];
        uint4 u0 = make_uint4(f2tf(f0.x * 0.125f), f2tf(f1.x * 0.125f),
                              f2tf(f0.y * 0.125f), f2tf(f1.y * 0.125f));
        uint4 u1 = make_uint4(f2tf(f0.z * 0.125f), f2tf(f1.z * 0.125f),
                              f2tf(f0.w * 0.125f), f2tf(f1.w * 0.125f));
        *(uint4*)&Qp[rg * UQ + dq * 4 + 0] = u0;
        *(uint4*)&Qp[rg * UQ + dq * 4 + 2] = u1;
    }

    float4 s[8], o[8];
#pragma unroll
    for (int t = 0; t < 8; t++) o[t] = make_float4(0.f, 0.f, 0.f, 0.f);
    float mrow0 = -INFINITY, mrow1 = -INFINITY, lrow0 = 0.f, lrow1 = 0.f;

    const int nkt = 2 * qt + 2;       // causal: key tiles of 64
    for (int kt = 0; kt < nkt; kt++) {
        const int k0 = kt * 64;

        __syncthreads();   // prior iter's reads of Kp/Vp/Pp done

        // ---- K pack: b-frag pairs {K[key][ks8+tig], K[key][ks8+tig+4]} ----
#pragma unroll
        for (int it = 0; it < 2; it++) {
            int e = tid + it * 256;    // 512 assignments
            int key = e & 63;
            int ks = e >> 6;           // 0..7
            const float* src = &Kb[(size_t)(k0 + key) * DKc + ks * 8];
            float4 f0 = *(const float4*)src;
            float4 f1 = *(const float4*)(src + 4);
            int m = ks * 8 + (key >> 3);
            int lb = (key & 7) * 4;
            uint4 u0 = make_uint4(f2tf(f0.x), f2tf(f1.x), f2tf(f0.y), f2tf(f1.y));
            uint4 u1 = make_uint4(f2tf(f0.z), f2tf(f1.z), f2tf(f0.w), f2tf(f1.w));
            *(uint4*)&Kp[m * 32 + lb + 0] = u0;
            *(uint4*)&Kp[m * 32 + lb + 2] = u1;
        }
        // ---- V pack: b-frag pairs {V[js8+tig][col], V[js8+tig+4][col]} ----
#pragma unroll
        for (int it = 0; it < 2; it++) {
            int e = tid + it * 256;    // 512 assignments
            int cq = e & 15;
            int tg = (e >> 4) & 3;
            int js = e >> 6;           // 0..7
            int r0 = k0 + js * 8 + tg;
            float4 f0 = *(const float4*)&Vb[(size_t)r0 * DKc + cq * 4];
            float4 f1 = *(const float4*)&Vb[(size_t)(r0 + 4) * DKc + cq * 4];
            float fa[4] = {f0.x, f0.y, f0.z, f0.w};
            float fb[4] = {f1.x, f1.y, f1.z, f1.w};
#pragma unroll
            for (int i = 0; i < 4; i++) {
                int col = cq * 4 + i;
                Vp[(js * 8 + (col >> 3)) * 32 + (col & 7) * 4 + tg] =
                    make_uint2(f2tf(fa[i]), f2tf(fb[i]));
            }
        }
        __syncthreads();

        // ---- S = (Q*scale) @ K^T : packed operands ----
#pragma unroll
        for (int t = 0; t < 8; t++) s[t] = make_float4(0.f, 0.f, 0.f, 0.f);
#pragma unroll
        for (int ks = 0; ks < 8; ks++) {
            uint2 a01 = Qp[(w * 8 + g) * UQ + ks * 8 + tig];
            uint2 a23 = Qp[(w * 8 + g) * UQ + ks * 8 + tig + 4];
#pragma unroll
            for (int t = 0; t < 8; t++)
                mma8(s[t], a01, a23, Kp[(ks * 8 + t) * 32 + lane]);
        }

        // Causal mask — needed only on the last two key tiles
        if (kt >= 2 * qt) {
            const int r0 = q0 + w * 16 + g;
            const int r1 = r0 + 8;
#pragma unroll
            for (int t = 0; t < 8; t++) {
                int c0 = k0 + t * 8 + 2 * tig;
                if (c0 > r0)     s[t].x = -INFINITY;
                if (c0 + 1 > r0) s[t].y = -INFINITY;
                if (c0 > r1)     s[t].z = -INFINITY;
                if (c0 + 1 > r1) s[t].w = -INFINITY;
            }
        }

        // ---- Online softmax on fragments ----
        float mx0 = -INFINITY, mx1 = -INFINITY;
#pragma unroll
        for (int t = 0; t < 8; t++) {
            mx0 = fmaxf(mx0, fmaxf(s[t].x, s[t].y));
            mx1 = fmaxf(mx1, fmaxf(s[t].z, s[t].w));
        }
        mx0 = fmaxf(mx0, __shfl_xor_sync(0xffffffffu, mx0, 1));
        mx0 = fmaxf(mx0, __shfl_xor_sync(0xffffffffu, mx0, 2));
        mx1 = fmaxf(mx1, __shfl_xor_sync(0xffffffffu, mx1, 1));
        mx1 = fmaxf(mx1, __shfl_xor_sync(0xffffffffu, mx1, 2));
        float mnew0 = fmaxf(mrow0, mx0);
        float mnew1 = fmaxf(mrow1, mx1);
        float cr0 = __expf(mrow0 - mnew0);
        float cr1 = __expf(mrow1 - mnew1);
        float sum0 = 0.f, sum1 = 0.f;
#pragma unroll
        for (int t = 0; t < 8; t++) {
            s[t].x = __expf(s[t].x - mnew0);
            s[t].y = __expf(s[t].y - mnew0);
            s[t].z = __expf(s[t].z - mnew1);
            s[t].w = __expf(s[t].w - mnew1);
            sum0 += s[t].x + s[t].y;
            sum1 += s[t].z + s[t].w;
        }
        sum0 += __shfl_xor_sync(0xffffffffu, sum0, 1);
        sum0 += __shfl_xor_sync(0xffffffffu, sum0, 2);
        sum1 += __shfl_xor_sync(0xffffffffu, sum1, 1);
        sum1 += __shfl_xor_sync(0xffffffffu, sum1, 2);
        lrow0 = lrow0 * cr0 + sum0;
        lrow1 = lrow1 * cr1 + sum1;
        mrow0 = mnew0;
        mrow1 = mnew1;
#pragma unroll
        for (int t = 0; t < 8; t++) {
            o[t].x *= cr0; o[t].y *= cr0;
            o[t].z *= cr1; o[t].w *= cr1;
        }

        // ---- Publish P directly in a-fragment pair order ----
        // pair {P[g][c], P[g+8][c]} at Pp[(w8+g)*UQ + c],  c = t*8 + 2*tig(+1)
#pragma unroll
        for (int t = 0; t < 8; t++) {
            uint4 u = make_uint4(f2tf(s[t].x), f2tf(s[t].z),
                                 f2tf(s[t].y), f2tf(s[t].w));
            *(uint4*)&Pp[(w * 8 + g) * UQ + t * 8 + 2 * tig] = u;
        }
        __syncthreads();

        // ---- O += P @ V : packed operands ----
#pragma unroll
        for (int js = 0; js < 8; js++) {
            uint2 a01 = Pp[(w * 8 + g) * UQ + js * 8 + tig];
            uint2 a23 = Pp[(w * 8 + g) * UQ + js * 8 + tig + 4];
#pragma unroll
            for (int t = 0; t < 8; t++)
                mma8(o[t], a01, a23, Vp[(js * 8 + t) * 32 + lane]);
        }
    }

    // Normalize and write out as [B,S,H*DK]
    const int b = bh >> 4;
    const int h = bh & 15;
    const float inv0 = 1.0f / lrow0;
    const float inv1 = 1.0f / lrow1;
    const size_t row0 = (size_t)(b * Sc + q0 + w * 16 + g) * Dc + h * DKc;
    const size_t row1 = row0 + 8 * Dc;
#pragma unroll
    for (int t = 0; t < 8; t++) {
        *(float2*)&Out[row0 + t * 8 + 2 * tig] =
            make_float2(o[t].x * inv0, o[t].y * inv0);
        *(float2*)&Out[row1 + t * 8 + 2 * tig] =
            make_float2(o[t].z * inv1, o[t].w * inv1);
    }
}

// ---------------------------------------------------------------------------
extern "C" void kernel_launch(void* const* d_in, const int* in_sizes, int n_in,
                              void* d_out, int out_size) {
    const float* x    = (const float*)d_in[0];   // [B,S,D]
    const float* Wqkv = (const float*)d_in[1];   // [D, 3D]
    const float* Wo   = (const float*)d_in[2];   // [D, D]
    float* out = (float*)d_out;

    float *qkv, *q, *k, *v, *attn;
    cudaGetSymbolAddress((void**)&qkv,  g_qkv);
    cudaGetSymbolAddress((void**)&q,    g_q);
    cudaGetSymbolAddress((void**)&k,    g_k);
    cudaGetSymbolAddress((void**)&v,    g_v);
    cudaGetSymbolAddress((void**)&attn, g_attn);

    // 0. RoPE tables (cheap, deterministic)
    rope_table_kernel<<<(Sc * 32) / 256, 256>>>();

    // 1. QKV projection: [4096,1024] @ [1024,3072]
    sgemm_kernel<<<dim3(3 * Dc / 128, BSc / 128), 256>>>(x, Wqkv, qkv, BSc, 3 * Dc, Dc);

    // 2. RoPE + head split (table-driven)
    rope_split_kernel<<<(Bc * Sc * Hc * DKc) / 256, 256>>>(qkv, q, k, v);

    // 3. Causal flash attention (tf32, fragment-packed smem)
    const int smem = (64 * UQ * 2 + 2048 * 2) * (int)sizeof(uint2);  // 102400 B
    cudaFuncSetAttribute(flash_attn_kernel,
                         cudaFuncAttributeMaxDynamicSharedMemorySize, smem);
    flash_attn_kernel<<<32 * QTILES, 256, smem>>>(q, k, v, attn);

    // 4. Output projection: [4096,1024] @ [1024,1024]
    sgemm_kernel<<<dim3(Dc / 128, BSc / 128), 256>>>(attn, Wo, out, BSc, Dc, Dc);
}

// round 8
// speedup vs baseline: 1.6065x; 1.6065x over previous
#include <cuda_runtime.h>
#include <math.h>

#define Bc 2
#define Sc 2048
#define Dc 1024
#define Hc 16
#define DKc 64
#define BSc (Bc*Sc)   // 4096

// Scratch (no allocations allowed)
__device__ float g_qkv[(size_t)BSc * 3 * Dc];      // [B,S,3,H,DK]
__device__ float g_q[(size_t)Bc*Hc*Sc*DKc];        // [B,H,S,DK]
__device__ float g_k[(size_t)Bc*Hc*Sc*DKc];
__device__ float g_v[(size_t)Bc*Hc*Sc*DKc];
__device__ float g_attn[(size_t)BSc * Dc];         // [B,S,D]
__device__ float g_ctab[Sc * 32];                  // RoPE cos table
__device__ float g_stab[Sc * 32];                  // RoPE sin table

__device__ __forceinline__ unsigned f2tf(float x) {
    unsigned r;
    asm("cvt.rna.tf32.f32 %0, %1;" : "=r"(r) : "f"(x));
    return r;
}

__device__ __forceinline__ void mma8(float4& d, uint2 a01, uint2 a23, uint2 b) {
    asm volatile(
        "mma.sync.aligned.m16n8k8.row.col.f32.tf32.tf32.f32 "
        "{%0,%1,%2,%3}, {%4,%5,%6,%7}, {%8,%9}, {%0,%1,%2,%3};\n"
        : "+f"(d.x), "+f"(d.y), "+f"(d.z), "+f"(d.w)
        : "r"(a01.x), "r"(a01.y), "r"(a23.x), "r"(a23.y), "r"(b.x), "r"(b.y));
}

// ---------------------------------------------------------------------------
// tf32 tensor-core GEMM: C[M,N] = A[M,K] @ B[K,N], tiles 128x128x32.
// 8 warps (2x4); warp computes 64x32 via 4x4 m16n8k8 mma per k-octet.
// Fragment-packed smem (same layouts as flash): all operand loads are LDS.64.
// Requires M%128==0, N%128==0, K%32==0.
// ---------------------------------------------------------------------------
#define AS 36   // A-pack rowgroup stride in uint2 (36 mod 32 = 4 -> bank-safe)

__global__ __launch_bounds__(256, 2)
void tgemm_kernel(const float* __restrict__ A,
                  const float* __restrict__ B,
                  float* __restrict__ C,
                  int M, int N, int K) {
    __shared__ uint2 Ap[64 * AS];    // pairs {A[r][k], A[r+8][k]} : [rowgrp][k]
    __shared__ uint2 Bp[64 * 32];    // pairs {B[k][n], B[k+4][n]} : [mma][lane]

    const int tid = threadIdx.x;
    const int lane = tid & 31;
    const int w = tid >> 5;          // warp 0..7
    const int g = lane >> 2;
    const int tig = lane & 3;
    const int wm = w >> 2;           // 0..1  (m offset wm*64)
    const int wn = w & 3;            // 0..3  (n offset wn*32)
    const int m0 = blockIdx.y << 7;
    const int n0 = blockIdx.x << 7;

    float4 acc[4][4];
#pragma unroll
    for (int i = 0; i < 4; i++)
#pragma unroll
        for (int j = 0; j < 4; j++) acc[i][j] = make_float4(0.f, 0.f, 0.f, 0.f);

    for (int k0 = 0; k0 < K; k0 += 32) {
        __syncthreads();   // previous iteration's reads done

        // ---- pack A tile (128x32) as a-fragment pairs ----
#pragma unroll
        for (int it = 0; it < 2; it++) {
            int e = tid + it * 256;          // [0,512)
            int rg = e >> 3;                 // rowgroup 0..63
            int kq = e & 7;                  // k-quad
            int r0 = m0 + (rg >> 3) * 16 + (rg & 7);
            const float* a0 = &A[(size_t)r0 * K + k0 + kq * 4];
            const float* a1 = &A[(size_t)(r0 + 8) * K + k0 + kq * 4];
            float4 f0 = *(const float4*)a0;
            float4 f1 = *(const float4*)a1;
            uint4 u0 = make_uint4(f2tf(f0.x), f2tf(f1.x), f2tf(f0.y), f2tf(f1.y));
            uint4 u1 = make_uint4(f2tf(f0.z), f2tf(f1.z), f2tf(f0.w), f2tf(f1.w));
            *(uint4*)&Ap[rg * AS + kq * 4 + 0] = u0;
            *(uint4*)&Ap[rg * AS + kq * 4 + 2] = u1;
        }
        // ---- pack B tile (32x128) as b-fragment pairs ----
#pragma unroll
        for (int it = 0; it < 2; it++) {
            int e = tid + it * 256;          // [0,512)
            int cq = e & 31;                 // n-quad 0..31
            int tg = (e >> 5) & 3;           // tig
            int ks = e >> 7;                 // k-octet 0..3
            int row = k0 + ks * 8 + tg;
            float4 f0 = *(const float4*)&B[(size_t)row * N + n0 + cq * 4];
            float4 f1 = *(const float4*)&B[(size_t)(row + 4) * N + n0 + cq * 4];
            float fa[4] = {f0.x, f0.y, f0.z, f0.w};
            float fb[4] = {f1.x, f1.y, f1.z, f1.w};
#pragma unroll
            for (int i = 0; i < 4; i++) {
                int col = cq * 4 + i;
                Bp[(ks * 16 + (col >> 3)) * 32 + (col & 7) * 4 + tg] =
                    make_uint2(f2tf(fa[i]), f2tf(fb[i]));
            }
        }
        __syncthreads();

        // ---- 16 mma per k-octet per warp ----
#pragma unroll
        for (int ks = 0; ks < 4; ks++) {
            uint2 bfr[4];
#pragma unroll
            for (int nt = 0; nt < 4; nt++)
                bfr[nt] = Bp[(ks * 16 + wn * 4 + nt) * 32 + lane];
#pragma unroll
            for (int mt = 0; mt < 4; mt++) {
                uint2 a01 = Ap[(wm * 32 + mt * 8 + g) * AS + ks * 8 + tig];
                uint2 a23 = Ap[(wm * 32 + mt * 8 + g) * AS + ks * 8 + tig + 4];
#pragma unroll
                for (int nt = 0; nt < 4; nt++)
                    mma8(acc[mt][nt], a01, a23, bfr[nt]);
            }
        }
    }

    // ---- epilogue ----
#pragma unroll
    for (int mt = 0; mt < 4; mt++) {
        int row = m0 + wm * 64 + mt * 16 + g;
#pragma unroll
        for (int nt = 0; nt < 4; nt++) {
            int col = n0 + wn * 32 + nt * 8 + 2 * tig;
            *(float2*)&C[(size_t)row * N + col] =
                make_float2(acc[mt][nt].x, acc[mt][nt].y);
            *(float2*)&C[(size_t)(row + 8) * N + col] =
                make_float2(acc[mt][nt].z, acc[mt][nt].w);
        }
    }
}

// ---------------------------------------------------------------------------
// RoPE table precompute (exact same math as reference path)
// ---------------------------------------------------------------------------
__global__ void rope_table_kernel() {
    int idx = blockIdx.x * blockDim.x + threadIdx.x;   // s*32 + d2
    int d2 = idx & 31;
    int s = idx >> 5;
    float invf = 1.0f / powf(10000.0f, (float)d2 * (1.0f / 32.0f));
    float ang = (float)s * invf;
    float sn, c;
    sincosf(ang, &sn, &c);
    g_ctab[idx] = c;
    g_stab[idx] = sn;
}

// ---------------------------------------------------------------------------
// RoPE + split heads, table-driven
// ---------------------------------------------------------------------------
__global__ void rope_split_kernel(const float* __restrict__ qkv,
                                  float* __restrict__ Q,
                                  float* __restrict__ Kp,
                                  float* __restrict__ V) {
    int idx = blockIdx.x * blockDim.x + threadIdx.x;  // [b][s][h][d]
    int d = idx & 63;
    int h = (idx >> 6) & (Hc - 1);
    int s = (idx >> 10) & (Sc - 1);
    int b = idx >> 21;

    const float* base = qkv + (size_t)(b * Sc + s) * 3 * Dc + h * DKc;
    float qv = base[d];
    float kv = base[Dc + d];
    float vv = base[2 * Dc + d];

    int d2 = d & 31;
    float c = g_ctab[s * 32 + d2];
    float sn = g_stab[s * 32 + d2];

    int dp = d ^ 32;            // rotate_half partner
    float qp = base[dp];
    float kp = base[Dc + dp];
    float sgn = (d < 32) ? -1.0f : 1.0f;

    float qo = qv * c + sgn * qp * sn;
    float ko = kv * c + sgn * kp * sn;

    size_t o = ((size_t)(b * Hc + h) * Sc + s) * DKc + d;
    Q[o] = qo;
    Kp[o] = ko;
    V[o] = vv;
}

// ---------------------------------------------------------------------------
// Flash attention (unchanged from R7 — measured 256us)
// ---------------------------------------------------------------------------
#define UQ 68               // a-fragment row-group stride in uint2 (bank-safe)
#define QTILES (Sc / 128)   // 16

__global__ __launch_bounds__(256, 2)
void flash_attn_kernel(const float* __restrict__ Q,
                       const float* __restrict__ K,
                       const float* __restrict__ V,
                       float* __restrict__ Out) {
    extern __shared__ uint2 sm2[];
    uint2* Qp = sm2;                  // [64 rowgrps][UQ]
    uint2* Pp = Qp + 64 * UQ;         // [64 rowgrps][UQ]
    uint2* Kp = Pp + 64 * UQ;         // [64 mma][32 lane]
    uint2* Vp = Kp + 2048;            // [64 mma][32 lane]

    const int tid = threadIdx.x;      // 256 threads
    const int lane = tid & 31;
    const int w = tid >> 5;           // warp 0..7
    const int g = lane >> 2;
    const int tig = lane & 3;

    // Heavy-first scheduling: qt descending with blockIdx.x
    const int id = blockIdx.x;
    const int bh = id & 31;                  // b*H + h
    const int qt = (QTILES - 1) - (id >> 5);
    const int q0 = qt * 128;

    const float* Qb = Q + (size_t)bh * Sc * DKc;
    const float* Kb = K + (size_t)bh * Sc * DKc;
    const float* Vb = V + (size_t)bh * Sc * DKc;

    // ---- Q pack prologue: pairs {Q[r][d], Q[r+8][d]}, pre-scaled ----
#pragma unroll
    for (int it = 0; it < 4; it++) {
        int e = tid + it * 256;        // 1024 assignments
        int rg = e >> 4;               // rowgroup 0..63
        int dq = e & 15;               // d-quad
        int r0 = q0 + (rg >> 3) * 16 + (rg & 7);
        float4 f0 = *(const float4*)&Qb[(size_t)r0 * DKc + dq * 4];
        float4 f1 = *(const float4*)&Qb[(size_t)(r0 + 8) * DKc + dq * 4];
        uint4 u0 = make_uint4(f2tf(f0.x * 0.125f), f2tf(f1.x * 0.125f),
                              f2tf(f0.y * 0.125f), f2tf(f1.y * 0.125f));
        uint4 u1 = make_uint4(f2tf(f0.z * 0.125f), f2tf(f1.z * 0.125f),
                              f2tf(f0.w * 0.125f), f2tf(f1.w * 0.125f));
        *(uint4*)&Qp[rg * UQ + dq * 4 + 0] = u0;
        *(uint4*)&Qp[rg * UQ + dq * 4 + 2] = u1;
    }

    float4 s[8], o[8];
#pragma unroll
    for (int t = 0; t < 8; t++) o[t] = make_float4(0.f, 0.f, 0.f, 0.f);
    float mrow0 = -INFINITY, mrow1 = -INFINITY, lrow0 = 0.f, lrow1 = 0.f;

    const int nkt = 2 * qt + 2;       // causal: key tiles of 64
    for (int kt = 0; kt < nkt; kt++) {
        const int k0 = kt * 64;

        __syncthreads();   // prior iter's reads of Kp/Vp/Pp done

        // ---- K pack: b-frag pairs ----
#pragma unroll
        for (int it = 0; it < 2; it++) {
            int e = tid + it * 256;    // 512 assignments
            int key = e & 63;
            int ks = e >> 6;           // 0..7
            const float* src = &Kb[(size_t)(k0 + key) * DKc + ks * 8];
            float4 f0 = *(const float4*)src;
            float4 f1 = *(const float4*)(src + 4);
            int m = ks * 8 + (key >> 3);
            int lb = (key & 7) * 4;
            uint4 u0 = make_uint4(f2tf(f0.x), f2tf(f1.x), f2tf(f0.y), f2tf(f1.y));
            uint4 u1 = make_uint4(f2tf(f0.z), f2tf(f1.z), f2tf(f0.w), f2tf(f1.w));
            *(uint4*)&Kp[m * 32 + lb + 0] = u0;
            *(uint4*)&Kp[m * 32 + lb + 2] = u1;
        }
        // ---- V pack: b-frag pairs ----
#pragma unroll
        for (int it = 0; it < 2; it++) {
            int e = tid + it * 256;    // 512 assignments
            int cq = e & 15;
            int tg = (e >> 4) & 3;
            int js = e >> 6;           // 0..7
            int r0 = k0 + js * 8 + tg;
            float4 f0 = *(const float4*)&Vb[(size_t)r0 * DKc + cq * 4];
            float4 f1 = *(const float4*)&Vb[(size_t)(r0 + 4) * DKc + cq * 4];
            float fa[4] = {f0.x, f0.y, f0.z, f0.w};
            float fb[4] = {f1.x, f1.y, f1.z, f1.w};
#pragma unroll
            for (int i = 0; i < 4; i++) {
                int col = cq * 4 + i;
                Vp[(js * 8 + (col >> 3)) * 32 + (col & 7) * 4 + tg] =
                    make_uint2(f2tf(fa[i]), f2tf(fb[i]));
            }
        }
        __syncthreads();

        // ---- S = (Q*scale) @ K^T ----
#pragma unroll
        for (int t = 0; t < 8; t++) s[t] = make_float4(0.f, 0.f, 0.f, 0.f);
#pragma unroll
        for (int ks = 0; ks < 8; ks++) {
            uint2 a01 = Qp[(w * 8 + g) * UQ + ks * 8 + tig];
            uint2 a23 = Qp[(w * 8 + g) * UQ + ks * 8 + tig + 4];
#pragma unroll
            for (int t = 0; t < 8; t++)
                mma8(s[t], a01, a23, Kp[(ks * 8 + t) * 32 + lane]);
        }

        // Causal mask — only on the last two key tiles
        if (kt >= 2 * qt) {
            const int r0 = q0 + w * 16 + g;
            const int r1 = r0 + 8;
#pragma unroll
            for (int t = 0; t < 8; t++) {
                int c0 = k0 + t * 8 + 2 * tig;
                if (c0 > r0)     s[t].x = -INFINITY;
                if (c0 + 1 > r0) s[t].y = -INFINITY;
                if (c0 > r1)     s[t].z = -INFINITY;
                if (c0 + 1 > r1) s[t].w = -INFINITY;
            }
        }

        // ---- Online softmax on fragments ----
        float mx0 = -INFINITY, mx1 = -INFINITY;
#pragma unroll
        for (int t = 0; t < 8; t++) {
            mx0 = fmaxf(mx0, fmaxf(s[t].x, s[t].y));
            mx1 = fmaxf(mx1, fmaxf(s[t].z, s[t].w));
        }
        mx0 = fmaxf(mx0, __shfl_xor_sync(0xffffffffu, mx0, 1));
        mx0 = fmaxf(mx0, __shfl_xor_sync(0xffffffffu, mx0, 2));
        mx1 = fmaxf(mx1, __shfl_xor_sync(0xffffffffu, mx1, 1));
        mx1 = fmaxf(mx1, __shfl_xor_sync(0xffffffffu, mx1, 2));
        float mnew0 = fmaxf(mrow0, mx0);
        float mnew1 = fmaxf(mrow1, mx1);
        float cr0 = __expf(mrow0 - mnew0);
        float cr1 = __expf(mrow1 - mnew1);
        float sum0 = 0.f, sum1 = 0.f;
#pragma unroll
        for (int t = 0; t < 8; t++) {
            s[t].x = __expf(s[t].x - mnew0);
            s[t].y = __expf(s[t].y - mnew0);
            s[t].z = __expf(s[t].z - mnew1);
            s[t].w = __expf(s[t].w - mnew1);
            sum0 += s[t].x + s[t].y;
            sum1 += s[t].z + s[t].w;
        }
        sum0 += __shfl_xor_sync(0xffffffffu, sum0, 1);
        sum0 += __shfl_xor_sync(0xffffffffu, sum0, 2);
        sum1 += __shfl_xor_sync(0xffffffffu, sum1, 1);
        sum1 += __shfl_xor_sync(0xffffffffu, sum1, 2);
        lrow0 = lrow0 * cr0 + sum0;
        lrow1 = lrow1 * cr1 + sum1;
        mrow0 = mnew0;
        mrow1 = mnew1;
#pragma unroll
        for (int t = 0; t < 8; t++) {
            o[t].x *= cr0; o[t].y *= cr0;
            o[t].z *= cr1; o[t].w *= cr1;
        }

        // ---- Publish P directly in a-fragment pair order ----
#pragma unroll
        for (int t = 0; t < 8; t++) {
            uint4 u = make_uint4(f2tf(s[t].x), f2tf(s[t].z),
                                 f2tf(s[t].y), f2tf(s[t].w));
            *(uint4*)&Pp[(w * 8 + g) * UQ + t * 8 + 2 * tig] = u;
        }
        __syncthreads();

        // ---- O += P @ V ----
#pragma unroll
        for (int js = 0; js < 8; js++) {
            uint2 a01 = Pp[(w * 8 + g) * UQ + js * 8 + tig];
            uint2 a23 = Pp[(w * 8 + g) * UQ + js * 8 + tig + 4];
#pragma unroll
            for (int t = 0; t < 8; t++)
                mma8(o[t], a01, a23, Vp[(js * 8 + t) * 32 + lane]);
        }
    }

    // Normalize and write out as [B,S,H*DK]
    const int b = bh >> 4;
    const int h = bh & 15;
    const float inv0 = 1.0f / lrow0;
    const float inv1 = 1.0f / lrow1;
    const size_t row0 = (size_t)(b * Sc + q0 + w * 16 + g) * Dc + h * DKc;
    const size_t row1 = row0 + 8 * Dc;
#pragma unroll
    for (int t = 0; t < 8; t++) {
        *(float2*)&Out[row0 + t * 8 + 2 * tig] =
            make_float2(o[t].x * inv0, o[t].y * inv0);
        *(float2*)&Out[row1 + t * 8 + 2 * tig] =
            make_float2(o[t].z * inv1, o[t].w * inv1);
    }
}

// ---------------------------------------------------------------------------
extern "C" void kernel_launch(void* const* d_in, const int* in_sizes, int n_in,
                              void* d_out, int out_size) {
    const float* x    = (const float*)d_in[0];   // [B,S,D]
    const float* Wqkv = (const float*)d_in[1];   // [D, 3D]
    const float* Wo   = (const float*)d_in[2];   // [D, D]
    float* out = (float*)d_out;

    float *qkv, *q, *k, *v, *attn;
    cudaGetSymbolAddress((void**)&qkv,  g_qkv);
    cudaGetSymbolAddress((void**)&q,    g_q);
    cudaGetSymbolAddress((void**)&k,    g_k);
    cudaGetSymbolAddress((void**)&v,    g_v);
    cudaGetSymbolAddress((void**)&attn, g_attn);

    // 0. RoPE tables
    rope_table_kernel<<<(Sc * 32) / 256, 256>>>();

    // 1. QKV projection: [4096,1024] @ [1024,3072]  (tf32 tensor cores)
    tgemm_kernel<<<dim3(3 * Dc / 128, BSc / 128), 256>>>(x, Wqkv, qkv, BSc, 3 * Dc, Dc);

    // 2. RoPE + head split (table-driven)
    rope_split_kernel<<<(Bc * Sc * Hc * DKc) / 256, 256>>>(qkv, q, k, v);

    // 3. Causal flash attention (tf32, fragment-packed smem)
    const int smem = (64 * UQ * 2 + 2048 * 2) * (int)sizeof(uint2);  // 102400 B
    cudaFuncSetAttribute(flash_attn_kernel,
                         cudaFuncAttributeMaxDynamicSharedMemorySize, smem);
    flash_attn_kernel<<<32 * QTILES, 256, smem>>>(q, k, v, attn);

    // 4. Output projection: [4096,1024] @ [1024,1024]  (tf32 tensor cores)
    tgemm_kernel<<<dim3(Dc / 128, BSc / 128), 256>>>(attn, Wo, out, BSc, Dc, Dc);
}